// round 10
// baseline (speedup 1.0000x reference)
#include <cuda_runtime.h>
#include <cuda_bf16.h>

// PowerSpectrum: out[n, l*512 + q*16 + p] = cg[l] * sum_m x_nu[l,n,m,q] * x_1[l,n,m,p]
// L=4, M=7, F_NU=32, F_1=16.
//
// Round-10: R9 (2-tile warp batching; best kernel-dur + DRAM% so far) plus
// L2 prefetch for the CTA one resident wave ahead (DIST = 148 SMs * 12 CTAs).
// Prefetch costs no registers/scoreboard/occupancy; it converts the next wave's
// DRAM-latency input LDGs into L2 hits, raising the chip-wide request rate that
// ncu shows is the remaining limiter (DRAM 79.7% with all pipes idle).
// Mapping unchanged: lane j owns p-quad (j&3)*4, q=(j>>2)+8k; STG.128s are
// contiguous 512B per warp.

#define PS_L  4
#define PS_M  7
#define PS_FN 32
#define PS_FP 16
#define OUT_PER_N (PS_L * PS_FN * PS_FP)   // 2048
#define F4_PER_TILE 84                     // 56 (x_nu) + 28 (x_1)
#define PF_DIST (148 * 12)                 // one resident wave ahead

__global__ __launch_bounds__(128, 12)
void ps_kernel(const float* __restrict__ x_nu,
               const float* __restrict__ x_1,
               float* __restrict__ out,
               int N)
{
    __shared__ float4 sm[4 * 2 * F4_PER_TILE];

    const int t = threadIdx.x;
    const int w = t >> 5;                  // warp 0..3 -> l
    const int j = t & 31;                  // lane
    const int l = w;
    const int n0 = blockIdx.x * 2;         // samples n0, n0+1

    // ---- L2 prefetch for CTA blockIdx.x + PF_DIST (its two tiles for this l) ----
    {
        const int pb = blockIdx.x + PF_DIST;
        if (pb < (N >> 1) && j < 22) {
            const int np = pb * 2;
            const char* pxA = reinterpret_cast<const char*>(x_nu) +
                              ((size_t)l * N + np) * (PS_M * PS_FN * 4);   // 896B tiles
            const char* p1A = reinterpret_cast<const char*>(x_1) +
                              ((size_t)l * N + np) * (PS_M * PS_FP * 4);   // 448B tiles
            const char* p;
            if      (j < 7)  p = pxA + j * 128;              // x_nu tile A (7 lines)
            else if (j < 11) p = p1A + (j - 7) * 128;        // x_1 tile A (4 lines)
            else if (j < 18) p = pxA + 896 + (j - 11) * 128; // x_nu tile B
            else             p = p1A + 448 + (j - 18) * 128; // x_1 tile B
            asm volatile("prefetch.global.L2 [%0];" :: "l"(p));
        }
    }

    const float4* gxA = reinterpret_cast<const float4*>(x_nu) + ((size_t)l * N + n0) * 56;
    const float4* g1A = reinterpret_cast<const float4*>(x_1)  + ((size_t)l * N + n0) * 28;
    const float4* gxB = gxA + 56;
    const float4* g1B = g1A + 28;

    float4* smA = sm + (w * 2 + 0) * F4_PER_TILE;
    float4* smB = sm + (w * 2 + 1) * F4_PER_TILE;

    // ---- issue all 6 independent LDGs, STS each immediately ----
    {
        const float4 a0 = gxA[j];
        const float4 a1 = (j < 24) ? gxA[32 + j] : g1A[j - 24];
        float4 a2; if (j < 20) a2 = g1A[8 + j];
        const float4 b0 = gxB[j];
        const float4 b1 = (j < 24) ? gxB[32 + j] : g1B[j - 24];
        float4 b2; if (j < 20) b2 = g1B[8 + j];

        smA[j]      = a0;
        smA[32 + j] = a1;
        if (j < 20) smA[64 + j] = a2;
        smB[j]      = b0;
        smB[32 + j] = b1;
        if (j < 20) smB[64 + j] = b2;
    }
    __syncwarp();

    const int qb = j >> 2;                 // q = qb + 8k
    const int pq = j & 3;                  // p = pq*4 .. pq*4+3
    const float cgs[PS_L] = {1.0f, 0.57735026918962576f,
                             0.44721359549995794f, 0.37796447300922722f};
    const float cg = cgs[l];

#pragma unroll
    for (int s = 0; s < 2; s++) {
        const float4* smw = (s == 0) ? smA : smB;
        const float*  an  = reinterpret_cast<const float*>(smw);   // [m*32 + q]
        const float4* bp  = smw + 56 + pq;                         // [m*4 + pq]

        float4 acc0 = make_float4(0.f, 0.f, 0.f, 0.f);
        float4 acc1 = acc0, acc2 = acc0, acc3 = acc0;

#pragma unroll
        for (int m = 0; m < PS_M; m++) {
            const float4 b = bp[m * 4];
            const float a0 = an[m * PS_FN + qb +  0];
            const float a1 = an[m * PS_FN + qb +  8];
            const float a2 = an[m * PS_FN + qb + 16];
            const float a3 = an[m * PS_FN + qb + 24];

            acc0.x = fmaf(a0, b.x, acc0.x);
            acc0.y = fmaf(a0, b.y, acc0.y);
            acc0.z = fmaf(a0, b.z, acc0.z);
            acc0.w = fmaf(a0, b.w, acc0.w);
            acc1.x = fmaf(a1, b.x, acc1.x);
            acc1.y = fmaf(a1, b.y, acc1.y);
            acc1.z = fmaf(a1, b.z, acc1.z);
            acc1.w = fmaf(a1, b.w, acc1.w);
            acc2.x = fmaf(a2, b.x, acc2.x);
            acc2.y = fmaf(a2, b.y, acc2.y);
            acc2.z = fmaf(a2, b.z, acc2.z);
            acc2.w = fmaf(a2, b.w, acc2.w);
            acc3.x = fmaf(a3, b.x, acc3.x);
            acc3.y = fmaf(a3, b.y, acc3.y);
            acc3.z = fmaf(a3, b.z, acc3.z);
            acc3.w = fmaf(a3, b.w, acc3.w);
        }

        acc0.x *= cg; acc0.y *= cg; acc0.z *= cg; acc0.w *= cg;
        acc1.x *= cg; acc1.y *= cg; acc1.z *= cg; acc1.w *= cg;
        acc2.x *= cg; acc2.y *= cg; acc2.z *= cg; acc2.w *= cg;
        acc3.x *= cg; acc3.y *= cg; acc3.z *= cg; acc3.w *= cg;

        float4* o = reinterpret_cast<float4*>(
            out + (size_t)(n0 + s) * OUT_PER_N + l * (PS_FN * PS_FP));
        o[j +  0] = acc0;
        o[j + 32] = acc1;
        o[j + 64] = acc2;
        o[j + 96] = acc3;
    }
}

extern "C" void kernel_launch(void* const* d_in, const int* in_sizes, int n_in,
                              void* d_out, int out_size)
{
    const float* x_nu = (const float*)d_in[0];
    const float* x_1  = (const float*)d_in[1];
    float* out = (float*)d_out;

    const int N = in_sizes[0] / (PS_L * PS_M * PS_FN);

    ps_kernel<<<N / 2, 128>>>(x_nu, x_1, out, N);
}

// round 11
// speedup vs baseline: 1.1793x; 1.1793x over previous
#include <cuda_runtime.h>
#include <cuda_bf16.h>

// PowerSpectrum: out[n, l*512 + q*16 + p] = cg[l] * sum_m x_nu[l,n,m,q] * x_1[l,n,m,p]
// L=4, M=7, F_NU=32, F_1=16.
//
// Round-11: R9 (2-tile warp batching) + L2 prefetch at SHORT distance.
// R10 proved prefetch lowers load latency (DRAM% rose to 81) but at one-wave
// distance ~45% of prefetched lines were evicted before use (+120MB re-reads).
// PF_DIST = 370 CTAs (~1/4 wave, ~1.8us lead): lead >> DRAM latency, but L2
// turnover in the window (~11MB) << capacity -> no eviction, no double reads.
// Mapping unchanged: lane j owns p-quad (j&3)*4, q=(j>>2)+8k; STG.128s are
// contiguous 512B per warp.

#define PS_L  4
#define PS_M  7
#define PS_FN 32
#define PS_FP 16
#define OUT_PER_N (PS_L * PS_FN * PS_FP)   // 2048
#define F4_PER_TILE 84                     // 56 (x_nu) + 28 (x_1)
#define PF_DIST 370                        // ~1/4 resident wave ahead

__global__ __launch_bounds__(128, 12)
void ps_kernel(const float* __restrict__ x_nu,
               const float* __restrict__ x_1,
               float* __restrict__ out,
               int N)
{
    __shared__ float4 sm[4 * 2 * F4_PER_TILE];

    const int t = threadIdx.x;
    const int w = t >> 5;                  // warp 0..3 -> l
    const int j = t & 31;                  // lane
    const int l = w;
    const int n0 = blockIdx.x * 2;         // samples n0, n0+1

    // ---- L2 prefetch for CTA blockIdx.x + PF_DIST (its two tiles for this l) ----
    {
        const int pb = blockIdx.x + PF_DIST;
        if (pb < (N >> 1) && j < 22) {
            const int np = pb * 2;
            const char* pxA = reinterpret_cast<const char*>(x_nu) +
                              ((size_t)l * N + np) * (PS_M * PS_FN * 4);   // 896B tiles
            const char* p1A = reinterpret_cast<const char*>(x_1) +
                              ((size_t)l * N + np) * (PS_M * PS_FP * 4);   // 448B tiles
            const char* p;
            if      (j < 7)  p = pxA + j * 128;              // x_nu tile A (7 lines)
            else if (j < 11) p = p1A + (j - 7) * 128;        // x_1 tile A (4 lines)
            else if (j < 18) p = pxA + 896 + (j - 11) * 128; // x_nu tile B
            else             p = p1A + 448 + (j - 18) * 128; // x_1 tile B
            asm volatile("prefetch.global.L2 [%0];" :: "l"(p));
        }
    }

    const float4* gxA = reinterpret_cast<const float4*>(x_nu) + ((size_t)l * N + n0) * 56;
    const float4* g1A = reinterpret_cast<const float4*>(x_1)  + ((size_t)l * N + n0) * 28;
    const float4* gxB = gxA + 56;
    const float4* g1B = g1A + 28;

    float4* smA = sm + (w * 2 + 0) * F4_PER_TILE;
    float4* smB = sm + (w * 2 + 1) * F4_PER_TILE;

    // ---- issue all 6 independent LDGs, STS each immediately ----
    {
        const float4 a0 = gxA[j];
        const float4 a1 = (j < 24) ? gxA[32 + j] : g1A[j - 24];
        float4 a2; if (j < 20) a2 = g1A[8 + j];
        const float4 b0 = gxB[j];
        const float4 b1 = (j < 24) ? gxB[32 + j] : g1B[j - 24];
        float4 b2; if (j < 20) b2 = g1B[8 + j];

        smA[j]      = a0;
        smA[32 + j] = a1;
        if (j < 20) smA[64 + j] = a2;
        smB[j]      = b0;
        smB[32 + j] = b1;
        if (j < 20) smB[64 + j] = b2;
    }
    __syncwarp();

    const int qb = j >> 2;                 // q = qb + 8k
    const int pq = j & 3;                  // p = pq*4 .. pq*4+3
    const float cgs[PS_L] = {1.0f, 0.57735026918962576f,
                             0.44721359549995794f, 0.37796447300922722f};
    const float cg = cgs[l];

#pragma unroll
    for (int s = 0; s < 2; s++) {
        const float4* smw = (s == 0) ? smA : smB;
        const float*  an  = reinterpret_cast<const float*>(smw);   // [m*32 + q]
        const float4* bp  = smw + 56 + pq;                         // [m*4 + pq]

        float4 acc0 = make_float4(0.f, 0.f, 0.f, 0.f);
        float4 acc1 = acc0, acc2 = acc0, acc3 = acc0;

#pragma unroll
        for (int m = 0; m < PS_M; m++) {
            const float4 b = bp[m * 4];
            const float a0 = an[m * PS_FN + qb +  0];
            const float a1 = an[m * PS_FN + qb +  8];
            const float a2 = an[m * PS_FN + qb + 16];
            const float a3 = an[m * PS_FN + qb + 24];

            acc0.x = fmaf(a0, b.x, acc0.x);
            acc0.y = fmaf(a0, b.y, acc0.y);
            acc0.z = fmaf(a0, b.z, acc0.z);
            acc0.w = fmaf(a0, b.w, acc0.w);
            acc1.x = fmaf(a1, b.x, acc1.x);
            acc1.y = fmaf(a1, b.y, acc1.y);
            acc1.z = fmaf(a1, b.z, acc1.z);
            acc1.w = fmaf(a1, b.w, acc1.w);
            acc2.x = fmaf(a2, b.x, acc2.x);
            acc2.y = fmaf(a2, b.y, acc2.y);
            acc2.z = fmaf(a2, b.z, acc2.z);
            acc2.w = fmaf(a2, b.w, acc2.w);
            acc3.x = fmaf(a3, b.x, acc3.x);
            acc3.y = fmaf(a3, b.y, acc3.y);
            acc3.z = fmaf(a3, b.z, acc3.z);
            acc3.w = fmaf(a3, b.w, acc3.w);
        }

        acc0.x *= cg; acc0.y *= cg; acc0.z *= cg; acc0.w *= cg;
        acc1.x *= cg; acc1.y *= cg; acc1.z *= cg; acc1.w *= cg;
        acc2.x *= cg; acc2.y *= cg; acc2.z *= cg; acc2.w *= cg;
        acc3.x *= cg; acc3.y *= cg; acc3.z *= cg; acc3.w *= cg;

        float4* o = reinterpret_cast<float4*>(
            out + (size_t)(n0 + s) * OUT_PER_N + l * (PS_FN * PS_FP));
        o[j +  0] = acc0;
        o[j + 32] = acc1;
        o[j + 64] = acc2;
        o[j + 96] = acc3;
    }
}

extern "C" void kernel_launch(void* const* d_in, const int* in_sizes, int n_in,
                              void* d_out, int out_size)
{
    const float* x_nu = (const float*)d_in[0];
    const float* x_1  = (const float*)d_in[1];
    float* out = (float*)d_out;

    const int N = in_sizes[0] / (PS_L * PS_M * PS_FN);

    ps_kernel<<<N / 2, 128>>>(x_nu, x_1, out, N);
}

// round 12
// speedup vs baseline: 1.1837x; 1.0037x over previous
#include <cuda_runtime.h>
#include <cuda_bf16.h>

// PowerSpectrum: out[n, l*512 + q*16 + p] = cg[l] * sum_m x_nu[l,n,m,q] * x_1[l,n,m,p]
// L=4, M=7, F_NU=32, F_1=16.
//
// Round-12: R9 dataflow (2 n-tiles batched per warp: 6 independent LDG.128 ->
// immediate STS -> syncwarp -> compute both tiles) with __launch_bounds__(128,16)
// forcing a 32-register budget so 64 warps/SM are resident (vs R9's 48 at 40
// regs). Goal: max BOTH axes of the request-rate product (warps x in-flight
// LDGs). Prefetch removed (R11 proved it neutral). Store mapping: lane j owns
// p-quad (j&3)*4, q=(j>>2)+8k -> every STG.128 is contiguous 512B.

#define PS_L  4
#define PS_M  7
#define PS_FN 32
#define PS_FP 16
#define OUT_PER_N (PS_L * PS_FN * PS_FP)   // 2048
#define F4_PER_TILE 84                     // 56 (x_nu) + 28 (x_1)

__global__ __launch_bounds__(128, 16)
void ps_kernel(const float* __restrict__ x_nu,
               const float* __restrict__ x_1,
               float* __restrict__ out,
               int N)
{
    __shared__ float4 sm[4 * 2 * F4_PER_TILE];

    const int t = threadIdx.x;
    const int w = t >> 5;                  // warp 0..3 -> l
    const int j = t & 31;                  // lane
    const int l = w;
    const int n0 = blockIdx.x * 2;         // samples n0, n0+1

    const float4* gxA = reinterpret_cast<const float4*>(x_nu) + ((size_t)l * N + n0) * 56;
    const float4* g1A = reinterpret_cast<const float4*>(x_1)  + ((size_t)l * N + n0) * 28;
    const float4* gxB = gxA + 56;
    const float4* g1B = g1A + 28;

    float4* smA = sm + (w * 2 + 0) * F4_PER_TILE;
    float4* smB = sm + (w * 2 + 1) * F4_PER_TILE;

    // ---- issue 6 independent LDGs, STS each as soon as its data arrives ----
    {
        const float4 a0 = gxA[j];
        const float4 a1 = (j < 24) ? gxA[32 + j] : g1A[j - 24];
        float4 a2; if (j < 20) a2 = g1A[8 + j];
        const float4 b0 = gxB[j];
        const float4 b1 = (j < 24) ? gxB[32 + j] : g1B[j - 24];
        float4 b2; if (j < 20) b2 = g1B[8 + j];

        smA[j]      = a0;
        smA[32 + j] = a1;
        if (j < 20) smA[64 + j] = a2;
        smB[j]      = b0;
        smB[32 + j] = b1;
        if (j < 20) smB[64 + j] = b2;
    }
    __syncwarp();

    const int qb = j >> 2;                 // q = qb + 8k
    const int pq = j & 3;                  // p = pq*4 .. pq*4+3
    const float cgs[PS_L] = {1.0f, 0.57735026918962576f,
                             0.44721359549995794f, 0.37796447300922722f};
    const float cg = cgs[l];

#pragma unroll
    for (int s = 0; s < 2; s++) {
        const float4* smw = (s == 0) ? smA : smB;
        const float*  an  = reinterpret_cast<const float*>(smw);   // [m*32 + q]
        const float4* bp  = smw + 56 + pq;                         // [m*4 + pq]

        float4 acc0 = make_float4(0.f, 0.f, 0.f, 0.f);
        float4 acc1 = acc0, acc2 = acc0, acc3 = acc0;

#pragma unroll
        for (int m = 0; m < PS_M; m++) {
            const float4 b = bp[m * 4];
            const float a0 = an[m * PS_FN + qb +  0];
            const float a1 = an[m * PS_FN + qb +  8];
            const float a2 = an[m * PS_FN + qb + 16];
            const float a3 = an[m * PS_FN + qb + 24];

            acc0.x = fmaf(a0, b.x, acc0.x);
            acc0.y = fmaf(a0, b.y, acc0.y);
            acc0.z = fmaf(a0, b.z, acc0.z);
            acc0.w = fmaf(a0, b.w, acc0.w);
            acc1.x = fmaf(a1, b.x, acc1.x);
            acc1.y = fmaf(a1, b.y, acc1.y);
            acc1.z = fmaf(a1, b.z, acc1.z);
            acc1.w = fmaf(a1, b.w, acc1.w);
            acc2.x = fmaf(a2, b.x, acc2.x);
            acc2.y = fmaf(a2, b.y, acc2.y);
            acc2.z = fmaf(a2, b.z, acc2.z);
            acc2.w = fmaf(a2, b.w, acc2.w);
            acc3.x = fmaf(a3, b.x, acc3.x);
            acc3.y = fmaf(a3, b.y, acc3.y);
            acc3.z = fmaf(a3, b.z, acc3.z);
            acc3.w = fmaf(a3, b.w, acc3.w);
        }

        acc0.x *= cg; acc0.y *= cg; acc0.z *= cg; acc0.w *= cg;
        acc1.x *= cg; acc1.y *= cg; acc1.z *= cg; acc1.w *= cg;
        acc2.x *= cg; acc2.y *= cg; acc2.z *= cg; acc2.w *= cg;
        acc3.x *= cg; acc3.y *= cg; acc3.z *= cg; acc3.w *= cg;

        float4* o = reinterpret_cast<float4*>(
            out + (size_t)(n0 + s) * OUT_PER_N + l * (PS_FN * PS_FP));
        o[j +  0] = acc0;
        o[j + 32] = acc1;
        o[j + 64] = acc2;
        o[j + 96] = acc3;
    }
}

extern "C" void kernel_launch(void* const* d_in, const int* in_sizes, int n_in,
                              void* d_out, int out_size)
{
    const float* x_nu = (const float*)d_in[0];
    const float* x_1  = (const float*)d_in[1];
    float* out = (float*)d_out;

    const int N = in_sizes[0] / (PS_L * PS_M * PS_FN);

    ps_kernel<<<N / 2, 128>>>(x_nu, x_1, out, N);
}